// round 3
// baseline (speedup 1.0000x reference)
#include <cuda_runtime.h>
#include <cstdint>

#define D 128
#define MAX_N 50176
#define MAX_E 810000

// Scratch (static __device__ allocations are the allowed scratch mechanism)
__device__ float g_agg[(size_t)MAX_N * D];
__device__ int   g_outdeg[MAX_N];
__device__ int   g_indeg[MAX_N];

// ---------------------------------------------------------------------------
// Kernel 1: degree counts (4 edges per thread, red-style atomics)
// ---------------------------------------------------------------------------
__global__ void degree_kernel(const int* __restrict__ src,
                              const int* __restrict__ dst, int E) {
    int i = (blockIdx.x * blockDim.x + threadIdx.x) * 4;
    #pragma unroll
    for (int j = 0; j < 4; j++) {
        int e = i + j;
        if (e < E) {
            atomicAdd(&g_outdeg[src[e]], 1);
            atomicAdd(&g_indeg[dst[e]], 1);
        }
    }
}

// ---------------------------------------------------------------------------
// Kernel 2: edge scatter.  One warp per edge; each lane handles a float4.
// g_agg[dst] += h[src] * out_deg[src]^-0.5 * 0.5^distance
// ---------------------------------------------------------------------------
__global__ void scatter_kernel(const float* __restrict__ h,
                               const int* __restrict__ src,
                               const int* __restrict__ dst,
                               const int* __restrict__ dist, int E) {
    int gid  = blockIdx.x * blockDim.x + threadIdx.x;
    int e    = gid >> 5;
    int lane = gid & 31;
    if (e >= E) return;

    int s = __ldg(src + e);
    int d = __ldg(dst + e);

    // lane 0 computes the scalar edge weight; broadcast to the warp
    float scale = 0.f;
    if (lane == 0) {
        int di = __ldg(dist + e);
        scale = rsqrtf((float)g_outdeg[s]) * exp2f(-(float)di);
    }
    scale = __shfl_sync(0xffffffffu, scale, 0);

    float4 v = reinterpret_cast<const float4*>(h + (size_t)s * D)[lane];
    float x = v.x * scale, y = v.y * scale, z = v.z * scale, w = v.w * scale;

    float* p = g_agg + (size_t)d * D + lane * 4;
    asm volatile("red.global.add.v4.f32 [%0], {%1,%2,%3,%4};"
                 :: "l"(p), "f"(x), "f"(y), "f"(z), "f"(w)
                 : "memory");
}

// ---------------------------------------------------------------------------
// Kernel 3: out = (g_agg * in_deg^-1.5) @ W + bias
// 128-row tile per block, full K=128, 256 threads, 8x8 microtile/thread.
// ---------------------------------------------------------------------------
__global__ __launch_bounds__(256)
void gemm_kernel(const float* __restrict__ Wm, const float* __restrict__ bias,
                 float* __restrict__ out, int N) {
    extern __shared__ float sm[];
    float* As = sm;            // [k][m] : D x 128, transposed
    float* Ws = sm + D * 128;  // [k][n] : D x D, row-major
    int tid  = threadIdx.x;
    int row0 = blockIdx.x * 128;

    // Load W tile (16384 floats, float4-vectorized)
    for (int i = tid * 4; i < D * D; i += 256 * 4)
        *(float4*)(Ws + i) = *(const float4*)(Wm + i);

    // Load A tile, scaled by in_deg^-1.5, stored transposed.
    for (int v = tid; v < 128 * (D / 4); v += 256) {
        int m  = v & 127;
        int k4 = (v >> 7) * 4;
        int grow = row0 + m;
        float4 a = make_float4(0.f, 0.f, 0.f, 0.f);
        float  s = 0.f;
        if (grow < N) {
            a = *(const float4*)(g_agg + (size_t)grow * D + k4);
            float id = (float)g_indeg[grow];
            s = rsqrtf(id) / id;     // id^-1.5
        }
        As[(k4 + 0) * 128 + m] = a.x * s;
        As[(k4 + 1) * 128 + m] = a.y * s;
        As[(k4 + 2) * 128 + m] = a.z * s;
        As[(k4 + 3) * 128 + m] = a.w * s;
    }
    __syncthreads();

    int tx = (tid & 15) * 8;   // N direction
    int ty = (tid >> 4) * 8;   // M direction

    float acc[8][8];
    #pragma unroll
    for (int i = 0; i < 8; i++)
        #pragma unroll
        for (int j = 0; j < 8; j++) acc[i][j] = 0.f;

    #pragma unroll 8
    for (int k = 0; k < D; k++) {
        float4 a0 = *(float4*)(As + k * 128 + ty);
        float4 a1 = *(float4*)(As + k * 128 + ty + 4);
        float4 b0 = *(float4*)(Ws + k * D + tx);
        float4 b1 = *(float4*)(Ws + k * D + tx + 4);
        float av[8] = {a0.x, a0.y, a0.z, a0.w, a1.x, a1.y, a1.z, a1.w};
        float bv[8] = {b0.x, b0.y, b0.z, b0.w, b1.x, b1.y, b1.z, b1.w};
        #pragma unroll
        for (int i = 0; i < 8; i++)
            #pragma unroll
            for (int j = 0; j < 8; j++)
                acc[i][j] = fmaf(av[i], bv[j], acc[i][j]);
    }

    float4 bb0 = *(const float4*)(bias + tx);
    float4 bb1 = *(const float4*)(bias + tx + 4);
    float bv[8] = {bb0.x, bb0.y, bb0.z, bb0.w, bb1.x, bb1.y, bb1.z, bb1.w};

    #pragma unroll
    for (int i = 0; i < 8; i++) {
        int grow = row0 + ty + i;
        if (grow < N) {
            float4 o0 = make_float4(acc[i][0] + bv[0], acc[i][1] + bv[1],
                                    acc[i][2] + bv[2], acc[i][3] + bv[3]);
            float4 o1 = make_float4(acc[i][4] + bv[4], acc[i][5] + bv[5],
                                    acc[i][6] + bv[6], acc[i][7] + bv[7]);
            *(float4*)(out + (size_t)grow * D + tx)     = o0;
            *(float4*)(out + (size_t)grow * D + tx + 4) = o1;
        }
    }
}

// ---------------------------------------------------------------------------
extern "C" void kernel_launch(void* const* d_in, const int* in_sizes, int n_in,
                              void* d_out, int out_size) {
    const float* h    = (const float*)d_in[0];
    const int*   src  = (const int*)  d_in[1];
    const int*   dst  = (const int*)  d_in[2];
    const int*   dist = (const int*)  d_in[3];
    const float* W    = (const float*)d_in[4];
    const float* bias = (const float*)d_in[5];
    float*       out  = (float*)d_out;

    int N = in_sizes[0] / D;
    int E = in_sizes[1];

    void *agg_p, *od_p, *id_p;
    cudaGetSymbolAddress(&agg_p, g_agg);
    cudaGetSymbolAddress(&od_p,  g_outdeg);
    cudaGetSymbolAddress(&id_p,  g_indeg);
    cudaMemsetAsync(agg_p, 0, (size_t)N * D * sizeof(float));
    cudaMemsetAsync(od_p,  0, N * sizeof(int));
    cudaMemsetAsync(id_p,  0, N * sizeof(int));

    degree_kernel<<<(E + 1023) / 1024, 256>>>(src, dst, E);

    long long sthreads = (long long)E * 32;
    scatter_kernel<<<(unsigned)((sthreads + 255) / 256), 256>>>(h, src, dst, dist, E);

    int smem_bytes = 2 * D * 128 * sizeof(float);  // 128 KB
    cudaFuncSetAttribute(gemm_kernel,
                         cudaFuncAttributeMaxDynamicSharedMemorySize, smem_bytes);
    gemm_kernel<<<(N + 127) / 128, 256, smem_bytes>>>(W, bias, out, N);
}